// round 9
// baseline (speedup 1.0000x reference)
#include <cuda_runtime.h>
#include <cstdint>

#define D 64
#define MAXN 100000
#define MAXE 1600000
#define WAVE 128
#define NT 256

#define ENT 384
#define ENW 12
#define EGRID 152
#define NPART (EGRID * ENW / 2)   // node partitions (2 warps each) = 912
#define RING 16                   // ring slots (power of 2)
#define LWS 68                    // padded row stride for sLW (transposed loop_W)
#define EOFFW 112                 // per-warp offset-table entries (>= npw+1)

// Scratch (static device globals; no runtime allocation allowed)
__device__ float g_h[(size_t)MAXN * D];   // h = node_h @ W_fc^T
__device__ int   g_deg[MAXN];
__device__ int   g_off[MAXN + 1];
__device__ int   g_cur[MAXN];
__device__ int   g_bsum[128];
__device__ int2  g_pes[MAXE];             // permuted (edge_idx, src)

typedef unsigned long long ull;

__device__ __forceinline__ ull fma2(ull a, ull b, ull c) {
    ull d;
    asm("fma.rn.f32x2 %0, %1, %2, %3;" : "=l"(d) : "l"(a), "l"(b), "l"(c));
    return d;
}
__device__ __forceinline__ float2 unpack2(ull v) {
    float2 r;
    asm("mov.b64 {%0, %1}, %2;" : "=f"(r.x), "=f"(r.y) : "l"(v));
    return r;
}
__device__ __forceinline__ void cp16(void* s, const void* g) {
    unsigned a = (unsigned)__cvta_generic_to_shared(s);
    asm volatile("cp.async.cg.shared.global [%0], [%1], 16;" :: "r"(a), "l"(g));
}
#define CP_COMMIT() asm volatile("cp.async.commit_group;" ::: "memory")
#define CP_WAIT1()  asm volatile("cp.async.wait_group 1;" ::: "memory")
#define CP_WAIT0()  asm volatile("cp.async.wait_group 0;" ::: "memory")
#define CP_WAIT5()  asm volatile("cp.async.wait_group 5;" ::: "memory")

// ---------------------------------------------------------------------------
__global__ void k_zero(int n4) {
    int i = blockIdx.x * blockDim.x + threadIdx.x;
    if (i < n4) ((int4*)g_deg)[i] = make_int4(0, 0, 0, 0);
}

__global__ void k_hist(const int* __restrict__ dst, int E) {
    int i = blockIdx.x * blockDim.x + threadIdx.x;
    if (i < E) atomicAdd(&g_deg[dst[i]], 1);
}

__global__ void k_scan1(int N) {
    __shared__ int s[1024];
    int t = threadIdx.x;
    int i = blockIdx.x * 1024 + t;
    int v = (i < N) ? g_deg[i] : 0;
    s[t] = v; __syncthreads();
#pragma unroll
    for (int d = 1; d < 1024; d <<= 1) {
        int u = (t >= d) ? s[t - d] : 0;
        __syncthreads();
        s[t] += u;
        __syncthreads();
    }
    if (i < N) g_off[i] = s[t] - v;
    if (t == 1023) g_bsum[blockIdx.x] = s[t];
}

__global__ void k_scan2(int nb, int N) {
    __shared__ int s[128];
    int t = threadIdx.x;
    int v = (t < nb) ? g_bsum[t] : 0;
    s[t] = v; __syncthreads();
#pragma unroll
    for (int d = 1; d < 128; d <<= 1) {
        int u = (t >= d) ? s[t - d] : 0;
        __syncthreads();
        s[t] += u;
        __syncthreads();
    }
    if (t < nb) g_bsum[t] = s[t] - v;
    if (t == 127) g_off[N] = s[127];
}

__global__ void k_scan3(int N) {
    int i = blockIdx.x * 1024 + threadIdx.x;
    if (i < N) {
        int o = g_off[i] + g_bsum[blockIdx.x];
        g_off[i] = o;
        g_cur[i] = o;
    }
}

__global__ void k_scatter(const int* __restrict__ src, const int* __restrict__ dst, int E) {
    int i = blockIdx.x * blockDim.x + threadIdx.x;
    if (i < E) {
        int d = dst[i];
        int pos = atomicAdd(&g_cur[d], 1);
        g_pes[pos] = make_int2(i, src[i]);
    }
}

// ---------------------------------------------------------------------------
// (k_node helpers, unchanged from R5)
__device__ __forceinline__ void load_w_rows(const float* __restrict__ W,
                                            int lane, ull* w0, ull* w1) {
    const ulonglong2* r0 = (const ulonglong2*)(W + (size_t)(2 * lane) * D);
    const ulonglong2* r1 = (const ulonglong2*)(W + (size_t)(2 * lane + 1) * D);
#pragma unroll
    for (int i = 0; i < 16; i++) {
        ulonglong2 v = r0[i]; w0[2 * i] = v.x; w0[2 * i + 1] = v.y;
        ulonglong2 u = r1[i]; w1[2 * i] = u.x; w1[2 * i + 1] = u.y;
    }
}

__device__ __forceinline__ float2 gemv2(const float* sRow, const ull* w0, const ull* w1) {
    const ulonglong2* xr = (const ulonglong2*)sRow;
    ull a00 = 0, a01 = 0, a10 = 0, a11 = 0;
#pragma unroll
    for (int i = 0; i < 16; i++) {
        ulonglong2 v = xr[i];
        a00 = fma2(v.x, w0[2 * i], a00);
        a10 = fma2(v.x, w1[2 * i], a10);
        a01 = fma2(v.y, w0[2 * i + 1], a01);
        a11 = fma2(v.y, w1[2 * i + 1], a11);
    }
    float2 f0 = unpack2(a00), f1 = unpack2(a01);
    float y0 = (f0.x + f1.x) + (f0.y + f1.y);
    f0 = unpack2(a10); f1 = unpack2(a11);
    float y1 = (f0.x + f1.x) + (f0.y + f1.y);
    return make_float2(y0, y1);
}

__device__ __forceinline__ void stage_rows(float* sXb, const float* __restrict__ G,
                                           size_t base, int nrows_total, int tid) {
#pragma unroll
    for (int i = 0; i < (WAVE * D / 4) / NT; i++) {
        int idx = tid + i * NT;
        size_t r = base + (idx >> 4);
        if (r < (size_t)nrows_total)
            cp16(sXb + (size_t)idx * 4, G + r * D + (size_t)(idx & 15) * 4);
    }
}

// ---------------------------------------------------------------------------
// g_h = node_h @ W_fc^T  (unchanged)
__global__ __launch_bounds__(NT, 1) void k_node(
    const float* __restrict__ node_h, const float* __restrict__ W, int N) {
    extern __shared__ float smem[];
    float* sX = smem;
    int tid = threadIdx.x, lane = tid & 31, warp = tid >> 5;
    ull w0[32], w1[32];
    load_w_rows(W, lane, w0, w1);

    int nw = (N + WAVE - 1) / WAVE;
    int w = blockIdx.x;
    if (w >= nw) return;
    stage_rows(sX, node_h, (size_t)w * WAVE, N, tid);
    CP_COMMIT();

    int buf = 0;
    for (; w < nw; w += gridDim.x, buf ^= 1) {
        int wn = w + gridDim.x;
        if (wn < nw) {
            stage_rows(sX + (size_t)(buf ^ 1) * WAVE * D, node_h, (size_t)wn * WAVE, N, tid);
            CP_COMMIT();
            CP_WAIT1();
        } else {
            CP_WAIT0();
        }
        __syncthreads();
        int rbase = w * WAVE;
        const float* sXb = sX + (size_t)buf * WAVE * D;
#pragma unroll 1
        for (int r = warp; r < WAVE; r += NT / 32) {
            if (rbase + r >= N) break;
            float2 y = gemv2(sXb + (size_t)r * D, w0, w1);
            *(float2*)(g_h + (size_t)(rbase + r) * D + 2 * lane) = y;
        }
        __syncthreads();
    }
}

// ---------------------------------------------------------------------------
// Fused sorted edge pass + final output.
// Each node range is processed by TWO independent warps, one per 32-channel
// half. One channel per thread: weights = 64 regs -> 12 warps/SM.
// Dynamic smem layout (float units):
#define X0   (D * LWS)                        // sLW: transposed loop_W
#define H0   (X0 + ENW * RING * D)            // per-warp x-row rings (full rows)
#define HN0  (H0 + ENW * RING * 32)           // per-warp h-half rings
#define OFF0 (HN0 + ENW * D)                  // per-warp hn staging
#define EDGE_SMEM_FLOATS (OFF0 + ENW * EOFFW)

__global__ __launch_bounds__(ENT, 1) void k_edge2(
    const float* __restrict__ edge_h, const float* __restrict__ W,
    const float* __restrict__ loopW, float* __restrict__ out, int N) {
    extern __shared__ __align__(16) float smem[];
    float* sLW = smem;   // sLW[c*LWS + k] = loopW[k*D + c]

    int tid = threadIdx.x, lane = tid & 31, warp = tid >> 5;
    float* sXw = smem + X0 + (size_t)warp * RING * D;    // full x rows
    float* sHw = smem + H0 + (size_t)warp * RING * 32;   // h halves
    float* sHn = smem + HN0 + (size_t)warp * D;          // full hn staging
    int*   sOf = (int*)(smem + OFF0) + (size_t)warp * EOFFW;

    for (int i = tid; i < D * D; i += ENT) {
        int k = i >> 6, c = i & 63;
        sLW[c * LWS + k] = loopW[k * D + c];
    }

    int gw = blockIdx.x * ENW + warp;
    int q = gw >> 1;            // node partition
    int half = gw & 1;          // channel half
    int c = half * 32 + lane;   // this thread's output channel

    // thread's weight row: W_fcr[c, :] as f32x2 pairs over k
    ull wr[32];
    {
        const ulonglong2* r0 = (const ulonglong2*)(W + (size_t)c * D);
#pragma unroll
        for (int i = 0; i < 16; i++) {
            ulonglong2 v = r0[i]; wr[2 * i] = v.x; wr[2 * i + 1] = v.y;
        }
    }
    __syncthreads();

    int npw = (N + NPART - 1) / NPART;
    int nbeg = q * npw;
    if (nbeg >= N) return;
    int nend = nbeg + npw; if (nend > N) nend = N;
    int nloc = nend - nbeg;

    for (int i = lane; i <= nloc; i += 32) sOf[i] = g_off[nbeg + i];
    __syncwarp();

    int kbeg = sOf[0];
    int kend_all = sOf[nloc];

    int n = nbeg;
    int kendn = sOf[1];
    // full-row staging pair for sHn (channels 2*lane, 2*lane+1)
    float2 hn2 = *(const float2*)(g_h + (size_t)n * D + 2 * lane);
    float accN = 0.f, accD = 0.f;

    auto do_flush = [&](int node) {
        __syncwarp();
        *(float2*)(sHn + 2 * lane) = hn2;
        __syncwarp();
        float v;
        if (accD > 0.f) {
            // self-loop: y = sum_k hn[k] * loopW[k][c]
            const ulonglong2* xr = (const ulonglong2*)sHn;                // broadcast
            const ulonglong2* ur = (const ulonglong2*)(sLW + (size_t)c * LWS);
            ull a0 = 0, a1 = 0, a2 = 0, a3 = 0;
#pragma unroll
            for (int i = 0; i < 8; i++) {
                ulonglong2 xv = xr[2 * i], xu = xr[2 * i + 1];
                ulonglong2 wv = ur[2 * i], wu = ur[2 * i + 1];
                a0 = fma2(xv.x, wv.x, a0); a1 = fma2(xv.y, wv.y, a1);
                a2 = fma2(xu.x, wu.x, a2); a3 = fma2(xu.y, wu.y, a3);
            }
            float2 f0 = unpack2(a0), f1 = unpack2(a1), f2 = unpack2(a2), f3 = unpack2(a3);
            float y = ((f0.x + f1.x) + (f0.y + f1.y)) + ((f2.x + f3.x) + (f2.y + f3.y));
            v = __fdividef(accN, accD) + y;
        } else {
            v = sHn[c];
        }
        out[(size_t)node * D + c] = fmaxf(v, 0.f);
    };

    auto consume = [&](int k) {
        while (k == kendn) {
            do_flush(n);
            n++;
            hn2 = *(const float2*)(g_h + (size_t)n * D + 2 * lane);
            accN = 0.f; accD = 0.f;
            kendn = sOf[n - nbeg + 1];
        }
        int slot = k & (RING - 1);
        float hv = sHw[slot * 32 + lane];
        const ulonglong2* xr = (const ulonglong2*)(sXw + slot * D);
        ull a0 = 0, a1 = 0, a2 = 0, a3 = 0;
#pragma unroll
        for (int i = 0; i < 8; i++) {
            ulonglong2 xv = xr[2 * i], xu = xr[2 * i + 1];
            a0 = fma2(xv.x, wr[4 * i + 0], a0);
            a1 = fma2(xv.y, wr[4 * i + 1], a1);
            a2 = fma2(xu.x, wr[4 * i + 2], a2);
            a3 = fma2(xu.y, wr[4 * i + 3], a3);
        }
        float2 f0 = unpack2(a0), f1 = unpack2(a1), f2 = unpack2(a2), f3 = unpack2(a3);
        float eh = ((f0.x + f1.x) + (f0.y + f1.y)) + ((f2.x + f3.x) + (f2.y + f3.y));
        float ex = __expf(eh);
        accD += ex;
        accN = fmaf(ex, hv + eh, accN);
    };

    // stage one edge: full x row (lanes 0-15, 16B each) + h half (lanes 16-23)
    auto stage_edge = [&](int e, int2 p) {
        int sl = e & (RING - 1);
        if (lane < 16) {
            cp16(sXw + sl * D + lane * 4, edge_h + (size_t)p.x * D + lane * 4);
        } else if (lane < 24) {
            int o = (lane - 16) * 4;
            cp16(sHw + sl * 32 + o, g_h + (size_t)p.y * D + half * 32 + o);
        }
    };

    // prologue: 6 pair-groups covering edges kbeg .. kbeg+11
#pragma unroll
    for (int g = 0; g < 6; g++) {
#pragma unroll
        for (int h = 0; h < 2; h++) {
            int e = kbeg + 2 * g + h;
            if (e < kend_all) stage_edge(e, g_pes[e]);
        }
        CP_COMMIT();
    }
    int2 pa = make_int2(0, 0), pb = make_int2(0, 0);
    if (kbeg + 12 < kend_all) pa = g_pes[kbeg + 12];
    if (kbeg + 13 < kend_all) pb = g_pes[kbeg + 13];

    for (int k = kbeg; k < kend_all; k += 2) {
        if (k + 12 < kend_all) stage_edge(k + 12, pa);
        if (k + 13 < kend_all) stage_edge(k + 13, pb);
        CP_COMMIT();
        if (k + 14 < kend_all) pa = g_pes[k + 14];
        if (k + 15 < kend_all) pb = g_pes[k + 15];
        CP_WAIT5();        // groups covering edges k..k+3 have landed
        __syncwarp();
        consume(k);
        if (k + 1 < kend_all) consume(k + 1);
    }
    for (;;) {
        do_flush(n);
        n++;
        if (n >= nend) break;
        hn2 = *(const float2*)(g_h + (size_t)n * D + 2 * lane);
        accN = 0.f; accD = 0.f;
    }
}

// ---------------------------------------------------------------------------
extern "C" void kernel_launch(void* const* d_in, const int* in_sizes, int n_in,
                              void* d_out, int out_size) {
    const float* node_h = (const float*)d_in[0];
    const float* edge_h = (const float*)d_in[1];
    const int*   src    = (const int*)d_in[2];
    const int*   dst    = (const int*)d_in[3];
    const float* W_fc   = (const float*)d_in[4];
    const float* W_fcr  = (const float*)d_in[5];
    const float* loop_W = (const float*)d_in[6];
    float* out = (float*)d_out;

    int N = in_sizes[0] / D;
    int E = in_sizes[2];
    if (N > MAXN) N = MAXN;
    if (E > MAXE) E = MAXE;

    const int ROW_SMEM  = 2 * WAVE * D * (int)sizeof(float);
    const int EDGE_SMEM = EDGE_SMEM_FLOATS * (int)sizeof(float);  // ~100 KB
    cudaFuncSetAttribute(k_node,  cudaFuncAttributeMaxDynamicSharedMemorySize, ROW_SMEM);
    cudaFuncSetAttribute(k_edge2, cudaFuncAttributeMaxDynamicSharedMemorySize, EDGE_SMEM);

    int nb = (N + 1023) / 1024;
    k_zero<<<((N + 3) / 4 + 255) / 256, 256>>>((N + 3) / 4);
    k_node<<<152, NT, ROW_SMEM>>>(node_h, W_fc, N);
    k_hist<<<(E + 255) / 256, 256>>>(dst, E);
    k_scan1<<<nb, 1024>>>(N);
    k_scan2<<<1, 128>>>(nb, N);
    k_scan3<<<nb, 1024>>>(N);
    k_scatter<<<(E + 255) / 256, 256>>>(src, dst, E);
    k_edge2<<<EGRID, ENT, EDGE_SMEM>>>(edge_h, W_fcr, loop_W, out, N);
}

// round 10
// speedup vs baseline: 1.1412x; 1.1412x over previous
#include <cuda_runtime.h>
#include <cstdint>

#define D 64
#define MAXN 100000
#define MAXE 1600000
#define WAVE 128
#define NT 256

#define RNW 8
#define RNT 256
#define RGRID 152
#define NPARTS (RGRID * RNW)      // 1216 node partitions
#define REOFF 84                  // >= ceil(MAXN/NPARTS)+1
#define LWS 68                    // padded row stride for sLW

// Scratch (static device globals; no runtime allocation allowed)
__device__ float g_h[(size_t)MAXN * D];     // h = node_h @ W_fc^T
__device__ float g_ehp[(size_t)MAXE * D];   // eh rows in dst-sorted order
__device__ int   g_deg[MAXN];
__device__ int   g_off[MAXN + 1];
__device__ int   g_cur[MAXN];
__device__ int   g_bsum[128];
__device__ int   g_pos[MAXE];               // edge -> sorted position
__device__ int   g_srcp[MAXE];              // src in sorted order

typedef unsigned long long ull;

__device__ __forceinline__ ull fma2(ull a, ull b, ull c) {
    ull d;
    asm("fma.rn.f32x2 %0, %1, %2, %3;" : "=l"(d) : "l"(a), "l"(b), "l"(c));
    return d;
}
__device__ __forceinline__ float2 unpack2(ull v) {
    float2 r;
    asm("mov.b64 {%0, %1}, %2;" : "=f"(r.x), "=f"(r.y) : "l"(v));
    return r;
}
__device__ __forceinline__ void cp16(void* s, const void* g) {
    unsigned a = (unsigned)__cvta_generic_to_shared(s);
    asm volatile("cp.async.cg.shared.global [%0], [%1], 16;" :: "r"(a), "l"(g));
}
__device__ __forceinline__ void cp4(void* s, const void* g) {
    unsigned a = (unsigned)__cvta_generic_to_shared(s);
    asm volatile("cp.async.ca.shared.global [%0], [%1], 4;" :: "r"(a), "l"(g));
}
#define CP_COMMIT() asm volatile("cp.async.commit_group;" ::: "memory")
#define CP_WAIT1()  asm volatile("cp.async.wait_group 1;" ::: "memory")
#define CP_WAIT0()  asm volatile("cp.async.wait_group 0;" ::: "memory")

// ---------------------------------------------------------------------------
__global__ void k_zero(int n4) {
    int i = blockIdx.x * blockDim.x + threadIdx.x;
    if (i < n4) ((int4*)g_deg)[i] = make_int4(0, 0, 0, 0);
}

__global__ void k_hist(const int* __restrict__ dst, int E) {
    int i = blockIdx.x * blockDim.x + threadIdx.x;
    if (i < E) atomicAdd(&g_deg[dst[i]], 1);
}

__global__ void k_scan1(int N) {
    __shared__ int s[1024];
    int t = threadIdx.x;
    int i = blockIdx.x * 1024 + t;
    int v = (i < N) ? g_deg[i] : 0;
    s[t] = v; __syncthreads();
#pragma unroll
    for (int d = 1; d < 1024; d <<= 1) {
        int u = (t >= d) ? s[t - d] : 0;
        __syncthreads();
        s[t] += u;
        __syncthreads();
    }
    if (i < N) g_off[i] = s[t] - v;
    if (t == 1023) g_bsum[blockIdx.x] = s[t];
}

__global__ void k_scan2(int nb, int N) {
    __shared__ int s[128];
    int t = threadIdx.x;
    int v = (t < nb) ? g_bsum[t] : 0;
    s[t] = v; __syncthreads();
#pragma unroll
    for (int d = 1; d < 128; d <<= 1) {
        int u = (t >= d) ? s[t - d] : 0;
        __syncthreads();
        s[t] += u;
        __syncthreads();
    }
    if (t < nb) g_bsum[t] = s[t] - v;
    if (t == 127) g_off[N] = s[127];
}

__global__ void k_scan3(int N) {
    int i = blockIdx.x * 1024 + threadIdx.x;
    if (i < N) {
        int o = g_off[i] + g_bsum[blockIdx.x];
        g_off[i] = o;
        g_cur[i] = o;
    }
}

__global__ void k_scatter(const int* __restrict__ src, const int* __restrict__ dst, int E) {
    int i = blockIdx.x * blockDim.x + threadIdx.x;
    if (i < E) {
        int d = dst[i];
        int pos = atomicAdd(&g_cur[d], 1);
        g_pos[i] = pos;
        g_srcp[pos] = src[i];
    }
}

// ---------------------------------------------------------------------------
__device__ __forceinline__ void load_w_rows(const float* __restrict__ W,
                                            int lane, ull* w0, ull* w1) {
    const ulonglong2* r0 = (const ulonglong2*)(W + (size_t)(2 * lane) * D);
    const ulonglong2* r1 = (const ulonglong2*)(W + (size_t)(2 * lane + 1) * D);
#pragma unroll
    for (int i = 0; i < 16; i++) {
        ulonglong2 v = r0[i]; w0[2 * i] = v.x; w0[2 * i + 1] = v.y;
        ulonglong2 u = r1[i]; w1[2 * i] = u.x; w1[2 * i + 1] = u.y;
    }
}

__device__ __forceinline__ float2 gemv2(const float* sRow, const ull* w0, const ull* w1) {
    const ulonglong2* xr = (const ulonglong2*)sRow;
    ull a00 = 0, a01 = 0, a10 = 0, a11 = 0;
#pragma unroll
    for (int i = 0; i < 16; i++) {
        ulonglong2 v = xr[i];
        a00 = fma2(v.x, w0[2 * i], a00);
        a10 = fma2(v.x, w1[2 * i], a10);
        a01 = fma2(v.y, w0[2 * i + 1], a01);
        a11 = fma2(v.y, w1[2 * i + 1], a11);
    }
    float2 f0 = unpack2(a00), f1 = unpack2(a01);
    float y0 = (f0.x + f1.x) + (f0.y + f1.y);
    f0 = unpack2(a10); f1 = unpack2(a11);
    float y1 = (f0.x + f1.x) + (f0.y + f1.y);
    return make_float2(y0, y1);
}

// dual-row gemv: 2x ILP, shared weights
__device__ __forceinline__ void gemv2x2(const float* rowA, const float* rowB,
                                        const ull* w0, const ull* w1,
                                        float2& ya, float2& yb) {
    const ulonglong2* xa = (const ulonglong2*)rowA;
    const ulonglong2* xb = (const ulonglong2*)rowB;
    ull a00 = 0, a01 = 0, a10 = 0, a11 = 0;
    ull b00 = 0, b01 = 0, b10 = 0, b11 = 0;
#pragma unroll
    for (int i = 0; i < 16; i++) {
        ulonglong2 va = xa[i], vb = xb[i];
        a00 = fma2(va.x, w0[2 * i], a00);
        a10 = fma2(va.x, w1[2 * i], a10);
        b00 = fma2(vb.x, w0[2 * i], b00);
        b10 = fma2(vb.x, w1[2 * i], b10);
        a01 = fma2(va.y, w0[2 * i + 1], a01);
        a11 = fma2(va.y, w1[2 * i + 1], a11);
        b01 = fma2(vb.y, w0[2 * i + 1], b01);
        b11 = fma2(vb.y, w1[2 * i + 1], b11);
    }
    float2 f0 = unpack2(a00), f1 = unpack2(a01);
    ya.x = (f0.x + f1.x) + (f0.y + f1.y);
    f0 = unpack2(a10); f1 = unpack2(a11);
    ya.y = (f0.x + f1.x) + (f0.y + f1.y);
    f0 = unpack2(b00); f1 = unpack2(b01);
    yb.x = (f0.x + f1.x) + (f0.y + f1.y);
    f0 = unpack2(b10); f1 = unpack2(b11);
    yb.y = (f0.x + f1.x) + (f0.y + f1.y);
}

__device__ __forceinline__ void stage_rows(float* sXb, const float* __restrict__ G,
                                           size_t base, int nrows_total, int tid) {
#pragma unroll
    for (int i = 0; i < (WAVE * D / 4) / NT; i++) {
        int idx = tid + i * NT;
        size_t r = base + (idx >> 4);
        if (r < (size_t)nrows_total)
            cp16(sXb + (size_t)idx * 4, G + r * D + (size_t)(idx & 15) * 4);
    }
}

// ---------------------------------------------------------------------------
// g_h = node_h @ W_fc^T
__global__ __launch_bounds__(NT, 1) void k_node(
    const float* __restrict__ node_h, const float* __restrict__ W, int N) {
    extern __shared__ float smem[];
    float* sX = smem;
    int tid = threadIdx.x, lane = tid & 31, warp = tid >> 5;
    ull w0[32], w1[32];
    load_w_rows(W, lane, w0, w1);

    int nw = (N + WAVE - 1) / WAVE;
    int w = blockIdx.x;
    if (w >= nw) return;
    stage_rows(sX, node_h, (size_t)w * WAVE, N, tid);
    CP_COMMIT();

    int buf = 0;
    for (; w < nw; w += gridDim.x, buf ^= 1) {
        int wn = w + gridDim.x;
        if (wn < nw) {
            stage_rows(sX + (size_t)(buf ^ 1) * WAVE * D, node_h, (size_t)wn * WAVE, N, tid);
            CP_COMMIT();
            CP_WAIT1();
        } else {
            CP_WAIT0();
        }
        __syncthreads();
        int rbase = w * WAVE;
        const float* sXb = sX + (size_t)buf * WAVE * D;
#pragma unroll 1
        for (int r = warp; r < WAVE; r += NT / 32) {
            if (rbase + r >= N) break;
            float2 y = gemv2(sXb + (size_t)r * D, w0, w1);
            *(float2*)(g_h + (size_t)(rbase + r) * D + 2 * lane) = y;
        }
        __syncthreads();
    }
}

// ---------------------------------------------------------------------------
// Phase A: eh = edge_h @ W_fcr^T, streamed in natural order, written to
// dst-sorted position g_pos[e]. Pure streaming GEMM, no gathers.
__global__ __launch_bounds__(NT, 1) void k_egemm(
    const float* __restrict__ edge_h, const float* __restrict__ W, int E) {
    extern __shared__ float smem[];
    float* sX = smem;                        // 2 * WAVE * D
    int* sPos = (int*)(smem + 2 * WAVE * D); // 2 * WAVE

    int tid = threadIdx.x, lane = tid & 31, warp = tid >> 5;
    ull w0[32], w1[32];
    load_w_rows(W, lane, w0, w1);

    int nw = (E + WAVE - 1) / WAVE;
    int w = blockIdx.x;
    if (w >= nw) return;
    stage_rows(sX, edge_h, (size_t)w * WAVE, E, tid);
    if (tid < WAVE) {
        size_t e = (size_t)w * WAVE + tid;
        if (e < (size_t)E) cp4(sPos + tid, g_pos + e);
    }
    CP_COMMIT();

    int buf = 0;
    for (; w < nw; w += gridDim.x, buf ^= 1) {
        int wn = w + gridDim.x;
        if (wn < nw) {
            int nb = buf ^ 1;
            stage_rows(sX + (size_t)nb * WAVE * D, edge_h, (size_t)wn * WAVE, E, tid);
            if (tid < WAVE) {
                size_t e = (size_t)wn * WAVE + tid;
                if (e < (size_t)E) cp4(sPos + nb * WAVE + tid, g_pos + e);
            }
            CP_COMMIT();
            CP_WAIT1();
        } else {
            CP_WAIT0();
        }
        __syncthreads();
        int rbase = w * WAVE;
        const float* sXb = sX + (size_t)buf * WAVE * D;
        const int* sPb = sPos + buf * WAVE;
#pragma unroll 1
        for (int r = warp; r < WAVE / 2; r += NT / 32) {   // pairs (r, r+64)
            int rA = r, rB = r + WAVE / 2;
            bool vA = rbase + rA < E, vB = rbase + rB < E;
            float2 ya, yb;
            gemv2x2(sXb + (size_t)rA * D, sXb + (size_t)rB * D, w0, w1, ya, yb);
            if (vA) {
                int p = sPb[rA];
                *(float2*)(g_ehp + (size_t)p * D + 2 * lane) = ya;
            }
            if (vB) {
                int p = sPb[rB];
                *(float2*)(g_ehp + (size_t)p * D + 2 * lane) = yb;
            }
        }
        __syncthreads();
    }
}

// ---------------------------------------------------------------------------
// Phase B: sorted streaming reduce + self-loop + relu -> out.
// Lane owns channels j0=2*lane, j0+1. ~14 instrs per edge.
__global__ __launch_bounds__(RNT) void k_reduce(
    const float* __restrict__ loopW, float* __restrict__ out, int N) {
    __shared__ float sLW[D * LWS];       // sLW[j*LWS+k] = loopW[k*D+j]
    __shared__ float sHn[RNW][D];
    __shared__ int   sOf[RNW][REOFF];

    int tid = threadIdx.x, lane = tid & 31, warp = tid >> 5;
    for (int i = tid; i < D * D; i += RNT) {
        int k = i >> 6, j = i & 63;
        sLW[j * LWS + k] = loopW[i];
    }
    __syncthreads();

    int j0 = 2 * lane;
    int gw = blockIdx.x * RNW + warp;
    int npw = (N + NPARTS - 1) / NPARTS;
    int nbeg = gw * npw;
    if (nbeg >= N) return;
    int nend = nbeg + npw; if (nend > N) nend = N;
    int nloc = nend - nbeg;

    for (int i = lane; i <= nloc; i += 32) sOf[warp][i] = g_off[nbeg + i];
    __syncwarp();

    int kbeg = sOf[warp][0];
    int kend = sOf[warp][nloc];

    int n = nbeg;
    int kendn = sOf[warp][1];
    float2 hnCur = *(const float2*)(g_h + (size_t)n * D + j0);
    float2 hnNxt = (n + 1 < nend) ? *(const float2*)(g_h + (size_t)(n + 1) * D + j0)
                                  : make_float2(0.f, 0.f);
    float2 accN = make_float2(0.f, 0.f), accD = make_float2(0.f, 0.f);

    auto do_flush = [&](int node) {
        __syncwarp();
        *(float2*)(&sHn[warp][j0]) = hnCur;
        __syncwarp();
        float v0, v1;
        if (accD.x > 0.f) {
            const ulonglong2* xr = (const ulonglong2*)sHn[warp];
            const ulonglong2* u0 = (const ulonglong2*)(sLW + (size_t)j0 * LWS);
            const ulonglong2* u1 = (const ulonglong2*)(sLW + (size_t)(j0 + 1) * LWS);
            ull a0 = 0, a1 = 0, b0 = 0, b1 = 0;
#pragma unroll
            for (int i = 0; i < 16; i++) {
                ulonglong2 v = xr[i];
                ulonglong2 p = u0[i], q = u1[i];
                a0 = fma2(v.x, p.x, a0); a1 = fma2(v.y, p.y, a1);
                b0 = fma2(v.x, q.x, b0); b1 = fma2(v.y, q.y, b1);
            }
            float2 f0 = unpack2(a0), f1 = unpack2(a1);
            float gj0 = (f0.x + f1.x) + (f0.y + f1.y);
            f0 = unpack2(b0); f1 = unpack2(b1);
            float gj1 = (f0.x + f1.x) + (f0.y + f1.y);
            v0 = __fdividef(accN.x, accD.x) + gj0;
            v1 = __fdividef(accN.y, accD.y) + gj1;
        } else {
            v0 = hnCur.x; v1 = hnCur.y;
        }
        *(float2*)(out + (size_t)node * D + j0) =
            make_float2(fmaxf(v0, 0.f), fmaxf(v1, 0.f));
    };

    auto advance = [&]() {
        do_flush(n);
        n++;
        hnCur = hnNxt;
        hnNxt = (n + 1 < nend) ? *(const float2*)(g_h + (size_t)(n + 1) * D + j0)
                               : make_float2(0.f, 0.f);
        accN = make_float2(0.f, 0.f); accD = make_float2(0.f, 0.f);
        kendn = sOf[warp][n - nbeg + 1];
    };

    auto consume = [&](int k, float2 ep, float2 hv) {
        while (k == kendn) advance();
        float ex0 = __expf(ep.x), ex1 = __expf(ep.y);
        accD.x += ex0; accD.y += ex1;
        accN.x = fmaf(ex0, hv.x + ep.x, accN.x);
        accN.y = fmaf(ex1, hv.y + ep.y, accN.y);
    };

    // software pipeline: src indices 2 batches ahead, data 1 batch ahead
    int sA[4], sB[4];
    float2 epC[4], hvC[4], epN[4], hvN[4];
#pragma unroll
    for (int i = 0; i < 4; i++) {
        sA[i] = (kbeg + i < kend) ? g_srcp[kbeg + i] : 0;
        sB[i] = (kbeg + 4 + i < kend) ? g_srcp[kbeg + 4 + i] : 0;
    }
#pragma unroll
    for (int i = 0; i < 4; i++) {
        int e = kbeg + i;
        if (e < kend) {
            epC[i] = *(const float2*)(g_ehp + (size_t)e * D + j0);
            hvC[i] = *(const float2*)(g_h + (size_t)sA[i] * D + j0);
        }
    }

    for (int k = kbeg; k < kend; k += 4) {
        // prefetch srcs for batch k+8 (into sA, no longer needed) and data k+4
#pragma unroll
        for (int i = 0; i < 4; i++) {
            int e = k + 8 + i;
            sA[i] = (e < kend) ? g_srcp[e] : 0;
        }
#pragma unroll
        for (int i = 0; i < 4; i++) {
            int e = k + 4 + i;
            if (e < kend) {
                epN[i] = *(const float2*)(g_ehp + (size_t)e * D + j0);
                hvN[i] = *(const float2*)(g_h + (size_t)sB[i] * D + j0);
            }
        }
        consume(k, epC[0], hvC[0]);
        if (k + 1 < kend) consume(k + 1, epC[1], hvC[1]);
        if (k + 2 < kend) consume(k + 2, epC[2], hvC[2]);
        if (k + 3 < kend) consume(k + 3, epC[3], hvC[3]);
        // rotate
#pragma unroll
        for (int i = 0; i < 4; i++) {
            epC[i] = epN[i]; hvC[i] = hvN[i];
            int t = sB[i]; sB[i] = sA[i]; sA[i] = t;
        }
    }
    // tail: flush current node, then remaining (empty) nodes
    while (n < nend) advance();
}

// ---------------------------------------------------------------------------
extern "C" void kernel_launch(void* const* d_in, const int* in_sizes, int n_in,
                              void* d_out, int out_size) {
    const float* node_h = (const float*)d_in[0];
    const float* edge_h = (const float*)d_in[1];
    const int*   src    = (const int*)d_in[2];
    const int*   dst    = (const int*)d_in[3];
    const float* W_fc   = (const float*)d_in[4];
    const float* W_fcr  = (const float*)d_in[5];
    const float* loop_W = (const float*)d_in[6];
    float* out = (float*)d_out;

    int N = in_sizes[0] / D;
    int E = in_sizes[2];
    if (N > MAXN) N = MAXN;
    if (E > MAXE) E = MAXE;

    const int ROW_SMEM = 2 * WAVE * D * (int)sizeof(float);
    const int GE_SMEM  = ROW_SMEM + 2 * WAVE * (int)sizeof(int);
    cudaFuncSetAttribute(k_node,  cudaFuncAttributeMaxDynamicSharedMemorySize, ROW_SMEM);
    cudaFuncSetAttribute(k_egemm, cudaFuncAttributeMaxDynamicSharedMemorySize, GE_SMEM);

    int nb = (N + 1023) / 1024;
    k_zero<<<((N + 3) / 4 + 255) / 256, 256>>>((N + 3) / 4);
    k_hist<<<(E + 255) / 256, 256>>>(dst, E);
    k_scan1<<<nb, 1024>>>(N);
    k_scan2<<<1, 128>>>(nb, N);
    k_scan3<<<nb, 1024>>>(N);
    k_scatter<<<(E + 255) / 256, 256>>>(src, dst, E);
    k_node<<<152, NT, ROW_SMEM>>>(node_h, W_fc, N);
    k_egemm<<<152, NT, GE_SMEM>>>(edge_h, W_fcr, E);
    k_reduce<<<RGRID, RNT>>>(loop_W, out, N);
}

// round 11
// speedup vs baseline: 1.2915x; 1.1317x over previous
#include <cuda_runtime.h>
#include <cstdint>

#define D 64
#define MAXN 100000
#define MAXE 1600000
#define WAVE 128
#define NT 256

#define ENT 256
#define ENW 8
#define RING 8          // ring slots (power of 2)
#define LWS 68          // padded row stride for sLW
#define EOFFW 128       // per-warp offset-table entries (>= npw+1 for smCount>=99)

// Scratch (static device globals; no runtime allocation allowed)
__device__ float g_h[(size_t)MAXN * D];   // h = node_h @ W_fc^T
__device__ int   g_deg[MAXN];
__device__ int   g_off[MAXN + 1];
__device__ int   g_cur[MAXN];
__device__ unsigned g_stat[1024];         // lookback statuses (flag<<30 | value)
__device__ int   g_bar;                   // software grid barrier counter
__device__ int2  g_pes[MAXE];             // permuted (edge_idx, src)

typedef unsigned long long ull;

__device__ __forceinline__ ull fma2(ull a, ull b, ull c) {
    ull d;
    asm("fma.rn.f32x2 %0, %1, %2, %3;" : "=l"(d) : "l"(a), "l"(b), "l"(c));
    return d;
}
__device__ __forceinline__ float2 unpack2(ull v) {
    float2 r;
    asm("mov.b64 {%0, %1}, %2;" : "=f"(r.x), "=f"(r.y) : "l"(v));
    return r;
}
__device__ __forceinline__ void cp16(void* s, const void* g) {
    unsigned a = (unsigned)__cvta_generic_to_shared(s);
    asm volatile("cp.async.cg.shared.global [%0], [%1], 16;" :: "r"(a), "l"(g));
}
__device__ __forceinline__ void cp8(void* s, const void* g) {
    unsigned a = (unsigned)__cvta_generic_to_shared(s);
    asm volatile("cp.async.ca.shared.global [%0], [%1], 8;" :: "r"(a), "l"(g));
}
#define CP_COMMIT() asm volatile("cp.async.commit_group;" ::: "memory")
#define CP_WAIT1()  asm volatile("cp.async.wait_group 1;" ::: "memory")
#define CP_WAIT0()  asm volatile("cp.async.wait_group 0;" ::: "memory")
#define CP_WAIT3()  asm volatile("cp.async.wait_group 3;" ::: "memory")

// ---------------------------------------------------------------------------
// [0] zero g_deg + lookback statuses + barrier counter
__global__ void k_zero(int n4, int nbscan) {
    int i = blockIdx.x * blockDim.x + threadIdx.x;
    if (i < n4) ((int4*)g_deg)[i] = make_int4(0, 0, 0, 0);
    if (i < nbscan) g_stat[i] = 0u;
    if (i == 0) g_bar = 0;
}

// [1] histogram of dst
__global__ void k_hist(const int* __restrict__ dst, int E) {
    int i = blockIdx.x * blockDim.x + threadIdx.x;
    if (i < E) atomicAdd(&g_deg[dst[i]], 1);
}

// ---------------------------------------------------------------------------
__device__ __forceinline__ void load_w_rows(const float* __restrict__ W,
                                            int lane, ull* w0, ull* w1) {
    const ulonglong2* r0 = (const ulonglong2*)(W + (size_t)(2 * lane) * D);
    const ulonglong2* r1 = (const ulonglong2*)(W + (size_t)(2 * lane + 1) * D);
#pragma unroll
    for (int i = 0; i < 16; i++) {
        ulonglong2 v = r0[i]; w0[2 * i] = v.x; w0[2 * i + 1] = v.y;
        ulonglong2 u = r1[i]; w1[2 * i] = u.x; w1[2 * i + 1] = u.y;
    }
}

__device__ __forceinline__ float2 gemv2(const float* sRow, const ull* w0, const ull* w1) {
    const ulonglong2* xr = (const ulonglong2*)sRow;
    ull a00 = 0, a01 = 0, a10 = 0, a11 = 0;
#pragma unroll
    for (int i = 0; i < 16; i++) {
        ulonglong2 v = xr[i];
        a00 = fma2(v.x, w0[2 * i], a00);
        a10 = fma2(v.x, w1[2 * i], a10);
        a01 = fma2(v.y, w0[2 * i + 1], a01);
        a11 = fma2(v.y, w1[2 * i + 1], a11);
    }
    float2 f0 = unpack2(a00), f1 = unpack2(a01);
    float y0 = (f0.x + f1.x) + (f0.y + f1.y);
    f0 = unpack2(a10); f1 = unpack2(a11);
    float y1 = (f0.x + f1.x) + (f0.y + f1.y);
    return make_float2(y0, y1);
}

__device__ __forceinline__ void stage_rows(float* sXb, const float* __restrict__ G,
                                           size_t base, int nrows_total, int tid) {
#pragma unroll
    for (int i = 0; i < (WAVE * D / 4) / NT; i++) {
        int idx = tid + i * NT;
        size_t r = base + (idx >> 4);
        if (r < (size_t)nrows_total)
            cp16(sXb + (size_t)idx * 4, G + r * D + (size_t)(idx & 15) * 4);
    }
}

// ---------------------------------------------------------------------------
// [2] combo: blocks [0, nbscan) = decoupled-lookback exclusive scan of g_deg;
//     blocks [nbscan, ...)      = node GEMM g_h = node_h @ W_fc^T.
__global__ __launch_bounds__(NT, 1) void k_combo(
    const float* __restrict__ node_h, const float* __restrict__ W,
    int N, int nbscan) {
    extern __shared__ float smem[];
    int tid = threadIdx.x;

    if ((int)blockIdx.x < nbscan) {
        // ---- scan role: tile of 1024 elements, 4 per thread ----
        __shared__ int ss[NT];
        __shared__ int sExc;
        int b = blockIdx.x;
        int base = b * 1024 + tid * 4;
        int4 v = make_int4(0, 0, 0, 0);
        if (base + 3 < N) v = *(const int4*)(g_deg + base);
        else {
            if (base < N)     v.x = g_deg[base];
            if (base + 1 < N) v.y = g_deg[base + 1];
            if (base + 2 < N) v.z = g_deg[base + 2];
        }
        int tsum = v.x + v.y + v.z + v.w;
        ss[tid] = tsum; __syncthreads();
#pragma unroll
        for (int d = 1; d < NT; d <<= 1) {
            int u = (tid >= d) ? ss[tid - d] : 0;
            __syncthreads();
            ss[tid] += u;
            __syncthreads();
        }
        int incl = ss[tid];
        int blockSum = ss[NT - 1];
        if (tid == 0) {
            int exc = 0;
            if (b == 0) {
                atomicExch(&g_stat[0], (2u << 30) | (unsigned)blockSum);
            } else {
                for (int j = b - 1; j >= 0; j--) {
                    unsigned s;
                    do { s = atomicAdd(&g_stat[j], 0u); } while ((s >> 30) == 0u);
                    exc += (int)(s & 0x3FFFFFFFu);
                    if ((s >> 30) == 2u) break;
                }
                atomicExch(&g_stat[b], (2u << 30) | (unsigned)(exc + blockSum));
            }
            sExc = exc;
            if (b == nbscan - 1) g_off[N] = exc + blockSum;
        }
        __syncthreads();
        int gbase = sExc + incl - tsum;   // global exclusive for this thread
        int o0 = gbase, o1 = o0 + v.x, o2 = o1 + v.y, o3 = o2 + v.z;
        if (base < N)     { g_off[base] = o0;     g_cur[base] = o0; }
        if (base + 1 < N) { g_off[base + 1] = o1; g_cur[base + 1] = o1; }
        if (base + 2 < N) { g_off[base + 2] = o2; g_cur[base + 2] = o2; }
        if (base + 3 < N) { g_off[base + 3] = o3; g_cur[base + 3] = o3; }
        return;
    }

    // ---- node GEMM role (R5 k_node, shifted block index) ----
    float* sX = smem;
    int lane = tid & 31, warp = tid >> 5;
    ull w0[32], w1[32];
    load_w_rows(W, lane, w0, w1);

    int ngrid = gridDim.x - nbscan;
    int nw = (N + WAVE - 1) / WAVE;
    int w = blockIdx.x - nbscan;
    if (w >= nw) return;
    stage_rows(sX, node_h, (size_t)w * WAVE, N, tid);
    CP_COMMIT();

    int buf = 0;
    for (; w < nw; w += ngrid, buf ^= 1) {
        int wn = w + ngrid;
        if (wn < nw) {
            stage_rows(sX + (size_t)(buf ^ 1) * WAVE * D, node_h, (size_t)wn * WAVE, N, tid);
            CP_COMMIT();
            CP_WAIT1();
        } else {
            CP_WAIT0();
        }
        __syncthreads();
        int rbase = w * WAVE;
        const float* sXb = sX + (size_t)buf * WAVE * D;
#pragma unroll 1
        for (int r = warp; r < WAVE; r += NT / 32) {
            if (rbase + r >= N) break;
            float2 y = gemv2(sXb + (size_t)r * D, w0, w1);
            *(float2*)(g_h + (size_t)(rbase + r) * D + 2 * lane) = y;
        }
        __syncthreads();
    }
}

// ---------------------------------------------------------------------------
// [3] edge2: scatter + one-wave software barrier + R5 fused sorted edge pass.
#define X0   (D * LWS)
#define H0   (X0 + ENW * RING * D)
#define HN0  (H0 + ENW * RING * D)
#define OFF0 (HN0 + ENW * D)
#define EDGE_SMEM_FLOATS (OFF0 + ENW * EOFFW)

__global__ __launch_bounds__(ENT, 1) void k_edge2(
    const float* __restrict__ edge_h, const int* __restrict__ src,
    const int* __restrict__ dst, const float* __restrict__ W,
    const float* __restrict__ loopW, float* __restrict__ out, int N, int E) {
    extern __shared__ __align__(16) float smem[];
    float* sLW = smem;

    int tid = threadIdx.x, lane = tid & 31, warp = tid >> 5;
    float* sXw = smem + X0 + (size_t)warp * RING * D;
    float* sHw = smem + H0 + (size_t)warp * RING * D;
    float* sHn = smem + HN0 + (size_t)warp * D;
    int*   sOf = (int*)(smem + OFF0) + (size_t)warp * EOFFW;

    // ---- phase 1: scatter (build dst-sorted (edge, src) pairs) ----
    for (int i = blockIdx.x * ENT + tid; i < E; i += gridDim.x * ENT) {
        int d = dst[i];
        int pos = atomicAdd(&g_cur[d], 1);
        g_pes[pos] = make_int2(i, src[i]);
    }

    // prep shared/regs while other blocks finish scattering
    for (int i = tid; i < D * D; i += ENT) {
        int k = i >> 6, j = i & 63;
        sLW[j * LWS + k] = loopW[i];
    }
    ull w0[32], w1[32];
    load_w_rows(W, lane, w0, w1);

    // ---- one-wave grid barrier (grid == #SMs, 1 block/SM resident) ----
    __threadfence();
    __syncthreads();
    if (tid == 0) {
        atomicAdd(&g_bar, 1);
        while (atomicAdd(&g_bar, 0) < (int)gridDim.x) { }
    }
    __syncthreads();

    // ---- phase 2: R5 fused sorted edge pass ----
    int wpg = gridDim.x * ENW;
    int gw = blockIdx.x * ENW + warp;
    int npw = (N + wpg - 1) / wpg;
    int nbeg = gw * npw;
    if (nbeg >= N) return;
    int nend = nbeg + npw; if (nend > N) nend = N;
    int nloc = nend - nbeg;

    for (int i = lane; i <= nloc; i += 32) sOf[i] = g_off[nbeg + i];
    __syncwarp();

    int kbeg = sOf[0];
    int kend_all = sOf[nloc];
    int j0 = 2 * lane;

    int n = nbeg;
    int kendn = sOf[1];
    float2 hn = *(const float2*)(g_h + (size_t)n * D + j0);
    float2 accN = make_float2(0.f, 0.f), accD = make_float2(0.f, 0.f);

    auto do_flush = [&](int node) {
        float v0, v1;
        if (accD.x > 0.f) {
            __syncwarp();
            *(float2*)(sHn + j0) = hn;
            __syncwarp();
            const ulonglong2* xr = (const ulonglong2*)sHn;
            const ulonglong2* u0 = (const ulonglong2*)(sLW + (size_t)j0 * LWS);
            const ulonglong2* u1 = (const ulonglong2*)(sLW + (size_t)(j0 + 1) * LWS);
            ull a0 = 0, a1 = 0, b0 = 0, b1 = 0;
#pragma unroll
            for (int i = 0; i < 16; i++) {
                ulonglong2 v = xr[i];
                ulonglong2 p = u0[i], q = u1[i];
                a0 = fma2(v.x, p.x, a0); a1 = fma2(v.y, p.y, a1);
                b0 = fma2(v.x, q.x, b0); b1 = fma2(v.y, q.y, b1);
            }
            float2 f0 = unpack2(a0), f1 = unpack2(a1);
            float gj0 = (f0.x + f1.x) + (f0.y + f1.y);
            f0 = unpack2(b0); f1 = unpack2(b1);
            float gj1 = (f0.x + f1.x) + (f0.y + f1.y);
            v0 = __fdividef(accN.x, accD.x) + gj0;
            v1 = __fdividef(accN.y, accD.y) + gj1;
        } else {
            v0 = hn.x; v1 = hn.y;
        }
        *(float2*)(out + (size_t)node * D + j0) =
            make_float2(fmaxf(v0, 0.f), fmaxf(v1, 0.f));
    };

    auto consume = [&](int k) {
        while (k == kendn) {
            do_flush(n);
            n++;
            hn = *(const float2*)(g_h + (size_t)n * D + j0);
            accN = make_float2(0.f, 0.f); accD = make_float2(0.f, 0.f);
            kendn = sOf[n - nbeg + 1];
        }
        int slot = k & (RING - 1);
        float2 hv = *(const float2*)(sHw + slot * D + j0);
        float2 eh = gemv2(sXw + slot * D, w0, w1);
        float ex0 = __expf(eh.x), ex1 = __expf(eh.y);
        accD.x += ex0; accD.y += ex1;
        accN.x = fmaf(ex0, hv.x + eh.x, accN.x);
        accN.y = fmaf(ex1, hv.y + eh.y, accN.y);
    };

    // pipeline prologue: 3 pair-groups covering edges kbeg .. kbeg+5
#pragma unroll
    for (int g = 0; g < 3; g++) {
#pragma unroll
        for (int h = 0; h < 2; h++) {
            int e = kbeg + 2 * g + h;
            if (e < kend_all) {
                int2 p = g_pes[e];
                int sl = e & (RING - 1);
                cp8(sXw + sl * D + j0, edge_h + (size_t)p.x * D + j0);
                cp8(sHw + sl * D + j0, g_h + (size_t)p.y * D + j0);
            }
        }
        CP_COMMIT();
    }
    int2 pa = make_int2(0, 0), pb = make_int2(0, 0);
    if (kbeg + 6 < kend_all) pa = g_pes[kbeg + 6];
    if (kbeg + 7 < kend_all) pb = g_pes[kbeg + 7];

    for (int k = kbeg; k < kend_all; k += 2) {
        if (k + 6 < kend_all) {
            int sl = (k + 6) & (RING - 1);
            cp8(sXw + sl * D + j0, edge_h + (size_t)pa.x * D + j0);
            cp8(sHw + sl * D + j0, g_h + (size_t)pa.y * D + j0);
        }
        if (k + 7 < kend_all) {
            int sl = (k + 7) & (RING - 1);
            cp8(sXw + sl * D + j0, edge_h + (size_t)pb.x * D + j0);
            cp8(sHw + sl * D + j0, g_h + (size_t)pb.y * D + j0);
        }
        CP_COMMIT();
        if (k + 8 < kend_all) pa = g_pes[k + 8];
        if (k + 9 < kend_all) pb = g_pes[k + 9];
        CP_WAIT3();
        __syncwarp();
        consume(k);
        if (k + 1 < kend_all) consume(k + 1);
    }
    for (;;) {
        do_flush(n);
        n++;
        if (n >= nend) break;
        hn = *(const float2*)(g_h + (size_t)n * D + j0);
        accN = make_float2(0.f, 0.f); accD = make_float2(0.f, 0.f);
    }
}

// ---------------------------------------------------------------------------
extern "C" void kernel_launch(void* const* d_in, const int* in_sizes, int n_in,
                              void* d_out, int out_size) {
    const float* node_h = (const float*)d_in[0];
    const float* edge_h = (const float*)d_in[1];
    const int*   src    = (const int*)d_in[2];
    const int*   dst    = (const int*)d_in[3];
    const float* W_fc   = (const float*)d_in[4];
    const float* W_fcr  = (const float*)d_in[5];
    const float* loop_W = (const float*)d_in[6];
    float* out = (float*)d_out;

    int N = in_sizes[0] / D;
    int E = in_sizes[2];
    if (N > MAXN) N = MAXN;
    if (E > MAXE) E = MAXE;

    int dev = 0;
    cudaGetDevice(&dev);
    int smCount = 148;
    cudaDeviceGetAttribute(&smCount, cudaDevAttrMultiProcessorCount, dev);
    if (smCount < 99) smCount = 99;      // EOFFW bound
    if (smCount > 512) smCount = 512;

    const int ROW_SMEM  = 2 * WAVE * D * (int)sizeof(float);
    const int EDGE_SMEM = EDGE_SMEM_FLOATS * (int)sizeof(float);  // ~57 KB
    cudaFuncSetAttribute(k_combo, cudaFuncAttributeMaxDynamicSharedMemorySize, ROW_SMEM);
    cudaFuncSetAttribute(k_edge2, cudaFuncAttributeMaxDynamicSharedMemorySize, EDGE_SMEM);

    int nbscan = (N + 1023) / 1024;      // <= 98
    int n4 = (N + 3) / 4;

    k_zero<<<(n4 + 255) / 256, 256>>>(n4, nbscan);
    k_hist<<<(E + 255) / 256, 256>>>(dst, E);
    k_combo<<<nbscan + smCount, NT, ROW_SMEM>>>(node_h, W_fc, N, nbscan);
    k_edge2<<<smCount, ENT, EDGE_SMEM>>>(edge_h, src, dst, W_fcr, loop_W, out, N, E);
}